// round 14
// baseline (speedup 1.0000x reference)
#include <cuda_runtime.h>
#include <cuda_bf16.h>
#include <math.h>

#define BB 32
#define TT 256
#define EE 256
#define HHD 256
#define KK 12
#define TSTART 10
#define TSTOP 11
#define NEGV (-10000.0f)

typedef unsigned long long ull;

// ---- f32x2 packed-FMA helpers (FFMA2; sm_103a) ----
__device__ __forceinline__ ull pk2(float x) {
    ull r; unsigned u = __float_as_uint(x);
    asm("mov.b64 %0, {%1, %1};" : "=l"(r) : "r"(u));
    return r;
}
__device__ __forceinline__ ull ffma2(ull a, ull b, ull c) {
    ull d;
    asm("fma.rn.f32x2 %0, %1, %2, %3;" : "=l"(d) : "l"(a), "l"(b), "l"(c));
    return d;
}
__device__ __forceinline__ float2 upk2(ull v) {
    unsigned a, b;
    asm("mov.b64 {%0, %1}, %2;" : "=r"(a), "=r"(b) : "l"(v));
    return make_float2(__uint_as_float(a), __uint_as_float(b));
}

// ------------------- static device scratch -------------------
__device__ float g_G2[2][TT][BB][1024];         // gate pre-activations [dir][t][b][jg], jg=g*256+u
__device__ float g_h[2][2][BB][HHD];            // h double buffer [parity][dir][b][u]
__device__ float g_Hcat[BB][TT][512];           // concatenated hidden states
__device__ float g_feats[BB][TT][KK];           // emission features
__device__ unsigned g_ctr[4][TT];               // per-(group,step) arrival counters

// ------------------- init: zero counters, seed h0 -------------------
__global__ void k_init(const float* __restrict__ h0) {
    int i = blockIdx.x * blockDim.x + threadIdx.x;
    if (i < 4 * TT) ((unsigned*)g_ctr)[i] = 0u;
    if (i < 2 * BB * HHD) ((float*)g_h[0])[i] = h0[i];   // parity 0 = input for t=0
}

// ------------------- fused gather + input-projection GEMM (FFMA2) ----------
// g_G2[dir][t][b][jg] = emb[tok(t,b,dir)] . Wih[jg,:] + bih[jg] + bhh[jg]
#define GP 68
__global__ void k_gemm(const int* __restrict__ sent, const int* __restrict__ lens,
                       const float* __restrict__ emb,
                       const float* __restrict__ Wf, const float* __restrict__ Wb,
                       const float* __restrict__ bihf, const float* __restrict__ bhhf,
                       const float* __restrict__ bihb, const float* __restrict__ bhhb) {
    __shared__ __align__(16) float Xs[16][GP];
    __shared__ __align__(16) float Ws[16][GP];
    __shared__ int toks[64];
    int dir  = blockIdx.z;
    int row0 = blockIdx.y * 64;
    int j0   = blockIdx.x * 64;
    const float* W = dir ? Wb : Wf;
    int tid = threadIdx.x;             // 256
    int tx = tid & 15, ty = tid >> 4;
    int lk = tid & 15, lr = tid >> 4;

    if (tid < 64) {
        int row = row0 + tid;
        int t = row >> 5, b = row & 31;
        int len = lens[b];
        int pos = dir ? ((t < len) ? (len - 1 - t) : t) : t;
        toks[tid] = sent[b * TT + pos];
    }
    __syncthreads();
    int myrow[4];
#pragma unroll
    for (int it = 0; it < 4; it++) myrow[it] = toks[lr + it * 16];

    ull accp[4][2];
#pragma unroll
    for (int i = 0; i < 4; i++) { accp[i][0] = 0ull; accp[i][1] = 0ull; }

    for (int k0 = 0; k0 < 256; k0 += 16) {
        __syncthreads();
#pragma unroll
        for (int it = 0; it < 4; it++) {
            int r = lr + it * 16;
            Xs[lk][r] = emb[myrow[it] * EE + k0 + lk];
            Ws[lk][r] = W[(j0 + r) * EE + k0 + lk];
        }
        __syncthreads();
#pragma unroll
        for (int kk = 0; kk < 16; kk++) {
            float4 xa = *(const float4*)&Xs[kk][ty * 4];
            ulonglong2 wp = *(const ulonglong2*)&Ws[kk][tx * 4];
            ull xx0 = pk2(xa.x), xx1 = pk2(xa.y), xx2 = pk2(xa.z), xx3 = pk2(xa.w);
            accp[0][0] = ffma2(wp.x, xx0, accp[0][0]);
            accp[0][1] = ffma2(wp.y, xx0, accp[0][1]);
            accp[1][0] = ffma2(wp.x, xx1, accp[1][0]);
            accp[1][1] = ffma2(wp.y, xx1, accp[1][1]);
            accp[2][0] = ffma2(wp.x, xx2, accp[2][0]);
            accp[2][1] = ffma2(wp.y, xx2, accp[2][1]);
            accp[3][0] = ffma2(wp.x, xx3, accp[3][0]);
            accp[3][1] = ffma2(wp.y, xx3, accp[3][1]);
        }
    }
    // epilogue: add biases (float4), coalesced STG.128 per row
    int jg0 = j0 + tx * 4;
    float4 bi = dir ? *(const float4*)&bihb[jg0] : *(const float4*)&bihf[jg0];
    float4 bh = dir ? *(const float4*)&bhhb[jg0] : *(const float4*)&bhhf[jg0];
    float4 bs = make_float4(bi.x + bh.x, bi.y + bh.y, bi.z + bh.z, bi.w + bh.w);
#pragma unroll
    for (int i = 0; i < 4; i++) {
        int row = row0 + ty * 4 + i;
        int t = row >> 5, b = row & 31;
        float2 a01 = upk2(accp[i][0]);
        float2 a23 = upk2(accp[i][1]);
        float4 v = make_float4(a01.x + bs.x, a01.y + bs.y, a23.x + bs.z, a23.y + bs.w);
        *(float4*)&g_G2[dir][t][b][jg0] = v;
    }
}

// ------------------- persistent recurrent LSTM (FFMA2, 256 thr, v-split) ----
__device__ __forceinline__ float fsig(float x) { return 1.f / (1.f + __expf(-x)); }

__global__ void __launch_bounds__(256, 1)
k_lstm(const float* __restrict__ Whhf, const float* __restrict__ Whhb,
       const float* __restrict__ c0, const int* __restrict__ lens) {
    // static shared: exactly 48KB
    __shared__ __align__(16) float w_sh[256 * 32];   // [v][u_l][gate] 32KB
    __shared__ __align__(16) float h_sh[16 * 256];   // [b_l][v] XOR-swizzled, 16KB (head aliased for partials)

    int bid  = blockIdx.x;
    int dir  = bid >> 6;
    int grp  = (bid >> 5) & 1;
    int grp4 = bid >> 5;               // 0..3 sync group (dir,grp)
    int uslc = bid & 31;
    int tid  = threadIdx.x;            // 256
    int half = tid >> 7;               // v-range half
    int wg   = tid & 127;
    int u_l  = wg & 7, b_l = wg >> 3;
    int u = uslc * 8 + u_l;
    int b = grp * 16 + b_l;
    const float* Whh = dir ? Whhb : Whhf;

    // load Whh slice (32 rows): w_sh[v*32 + ul*4 + g] = Whh[(g*256 + uslc*8 + ul)][v]
    for (int i = tid; i < 32 * 256; i += 256) {
        int v = i & 255;
        int ug = i >> 8;                 // ul*4 + g
        int ul2 = ug >> 2, g2 = ug & 3;
        w_sh[v * 32 + ul2 * 4 + g2] = Whh[(g2 * 256 + uslc * 8 + ul2) * HHD + v];
    }
    float c = 0.f;
    int len = lens[b];
    if (!half) c = c0[(dir * BB + b) * HHD + u];
    int xsw = b_l & 3;
    const ulonglong2* w16 = (const ulonglong2*)w_sh;
    const unsigned* myctr = &g_ctr[grp4][0];
    int vbase = half << 7;
    __syncthreads();

    for (int t = 0; t < TT; t++) {
        // prefetch gate pre-activations (independent of h); half 0 only
        float gp0 = 0.f, gp1 = 0.f, gp2 = 0.f, gp3 = 0.f;
        if (!half) {
            const float* gbase = &g_G2[dir][t][b][0];
            gp0 = __ldg(gbase + u);
            gp1 = __ldg(gbase + 256 + u);
            gp2 = __ldg(gbase + 512 + u);
            gp3 = __ldg(gbase + 768 + u);
        }

        // wait for all 32 peer blocks to have produced step-t input
        if (t > 0 && tid == 0) {
            unsigned v;
            const unsigned* fp = myctr + (t - 1);
            do {
                asm volatile("ld.acquire.gpu.global.u32 %0, [%1];"
                             : "=r"(v) : "l"(fp) : "memory");
            } while (v < 32u);
        }
        __syncthreads();

        // restage h (16 batches x 256) from L2-coherent buffer, XOR-swizzled
        {
            const float4* src = (const float4*)&g_h[t & 1][dir][grp * 16][0];
            for (int i = tid; i < 1024; i += 256) {
                float4 hv = __ldcg(src + i);
                int bb2 = i >> 6, cc = i & 63;
                *(float4*)&h_sh[bb2 * 256 + ((cc ^ (bb2 & 3)) << 2)] = hv;
            }
        }
        __syncthreads();

        // GEMV half: 4 gates x 128 v, packed as (i,f) and (g,o) f32x2 accumulators
        ull aif = 0ull, ago = 0ull;
        const float* hrow = h_sh + b_l * 256;
#pragma unroll 4
        for (int vv = 0; vv < 128; vv += 4) {
            int v = vbase + vv;
            float4 h4 = *(const float4*)&hrow[(((v >> 2) ^ xsw) << 2)];
            ulonglong2 w0 = w16[(v + 0) * 8 + u_l];
            ulonglong2 w1 = w16[(v + 1) * 8 + u_l];
            ulonglong2 w2 = w16[(v + 2) * 8 + u_l];
            ulonglong2 w3 = w16[(v + 3) * 8 + u_l];
            ull hx = pk2(h4.x), hy = pk2(h4.y), hz = pk2(h4.z), hw = pk2(h4.w);
            aif = ffma2(w0.x, hx, aif); ago = ffma2(w0.y, hx, ago);
            aif = ffma2(w1.x, hy, aif); ago = ffma2(w1.y, hy, ago);
            aif = ffma2(w2.x, hz, aif); ago = ffma2(w2.y, hz, ago);
            aif = ffma2(w3.x, hw, aif); ago = ffma2(w3.y, hw, ago);
        }

        __syncthreads();                       // all h_sh reads done
        if (half) {
            ulonglong2 p; p.x = aif; p.y = ago;
            ((ulonglong2*)h_sh)[wg] = p;       // alias head of h_sh (2KB)
        }
        __syncthreads();
        if (!half) {
            ulonglong2 p = ((ulonglong2*)h_sh)[wg];
            float2 a0 = upk2(aif), g0 = upk2(ago);
            float2 a1 = upk2(p.x), g1 = upk2(p.y);
            float ai = a0.x + a1.x + gp0;
            float af = a0.y + a1.y + gp1;
            float ag = g0.x + g1.x + gp2;
            float ao = g0.y + g1.y + gp3;
            float ig = fsig(ai), fg = fsig(af), gg = tanhf(ag), og = fsig(ao);
            c = fg * c + ig * gg;
            float h = og * tanhf(c);
            __stcg(&g_h[(t + 1) & 1][dir][b][u], h);
            int pos = dir ? ((t < len) ? (len - 1 - t) : t) : t;
            g_Hcat[b][pos][dir * 256 + u] = h;
        }
        __syncthreads();   // half-0 stores done (happens-before the release below)
        if (tid == 0) {
            asm volatile("red.release.gpu.global.add.u32 [%0], %1;"
                         :: "l"(myctr + t), "r"(1u) : "memory");
        }
    }
}

// ------------------- emission features: Hcat @ W_out^T + b_out -------------------
__global__ void k_feats(const float* __restrict__ Wout, const float* __restrict__ bout) {
    __shared__ __align__(16) float Wsh[12 * 516];
    __shared__ __align__(16) float Hsh[8 * 516];
    int blk = blockIdx.x;              // 1024 blocks, 8 rows each
    int tid = threadIdx.x;             // 128
    for (int i = tid; i < 12 * 512; i += 128) Wsh[(i >> 9) * 516 + (i & 511)] = Wout[i];
    int row0 = blk * 8;                // row = b*256 + t
    for (int i = tid; i < 8 * 512; i += 128)
        Hsh[(i >> 9) * 516 + (i & 511)] = ((const float*)g_Hcat)[(row0 + (i >> 9)) * 512 + (i & 511)];
    __syncthreads();
    if (tid < 96) {
        int rl = tid / 12, k = tid % 12;
        float s0 = bout[k], s1 = 0.f, s2 = 0.f, s3 = 0.f;
        const float* wr = &Wsh[k * 516];
        const float* hr = &Hsh[rl * 516];
#pragma unroll 8
        for (int hh = 0; hh < 512; hh += 4) {
            float4 a = *(const float4*)&wr[hh];
            float4 bb4 = *(const float4*)&hr[hh];
            s0 += a.x * bb4.x; s1 += a.y * bb4.y; s2 += a.z * bb4.z; s3 += a.w * bb4.w;
        }
        ((float*)g_feats)[(row0 + rl) * 12 + k] = (s0 + s1) + (s2 + s3);
    }
}

// ------------------- Viterbi DP + backtrace -------------------
__global__ void k_viterbi(const float* __restrict__ trans, const int* __restrict__ lens,
                          float* __restrict__ out) {
    __shared__ float tr[144];
    __shared__ float fv[8][13];
    __shared__ unsigned char bp[TT][8][12];
    __shared__ int lsh[8];
    int b0 = blockIdx.x * 8;
    int tid = threadIdx.x;             // 128
    for (int i = tid; i < 144; i += 128) tr[i] = trans[i];
    if (tid < 8) lsh[tid] = lens[b0 + tid];
    int rl = tid / 12, k = tid % 12;
    bool act = tid < 96;
    if (act) fv[rl][k] = (k == TSTART) ? 0.f : NEGV;
    __syncthreads();

    float trk[12];
    if (act) {
#pragma unroll
        for (int p = 0; p < 12; p++) trk[p] = tr[k * 12 + p];
    }
    int len = act ? lsh[rl] : 0;
    int bg = b0 + rl;

    for (int t = 0; t < TT; t++) {
        float nf = 0.f;
        if (act) {
            float feat = ((const float*)g_feats)[(bg * TT + t) * 12 + k];
            float best = fv[rl][0] + trk[0];
            int bpi = 0;
#pragma unroll
            for (int p = 1; p < 12; p++) {
                float s = fv[rl][p] + trk[p];
                if (s > best) { best = s; bpi = p; }   // strict > => first max (jnp.argmax)
            }
            bp[t][rl][k] = (unsigned char)bpi;
            nf = (t < len) ? (best + feat) : fv[rl][k];
        }
        __syncthreads();
        if (act) fv[rl][k] = nf;
        __syncthreads();
    }

    if (tid < 8) {
        int r = tid;
        int bgl = b0 + r;
        int ln = lsh[r];
        float best = fv[r][0] + tr[TSTOP * 12 + 0];
        int tag = 0;
        for (int p = 1; p < 12; p++) {
            float s = fv[r][p] + tr[TSTOP * 12 + p];
            if (s > best) { best = s; tag = p; }
        }
        out[bgl] = best;                               // path score
        for (int t = TT - 1; t >= 0; t--) {
            bool m = t < ln;
            out[BB + bgl * TT + t] = m ? (float)tag : -1.0f;
            if (m) tag = bp[t][r][tag];
        }
    }
}

// ------------------- launch -------------------
extern "C" void kernel_launch(void* const* d_in, const int* in_sizes, int n_in,
                              void* d_out, int out_size) {
    const int*   sent  = (const int*)d_in[0];
    const int*   lens  = (const int*)d_in[1];
    const float* emb   = (const float*)d_in[2];
    const float* Wihf  = (const float*)d_in[3];
    const float* Whhf  = (const float*)d_in[4];
    const float* bihf  = (const float*)d_in[5];
    const float* bhhf  = (const float*)d_in[6];
    const float* Wihb  = (const float*)d_in[7];
    const float* Whhb  = (const float*)d_in[8];
    const float* bihb  = (const float*)d_in[9];
    const float* bhhb  = (const float*)d_in[10];
    const float* h0    = (const float*)d_in[11];
    const float* c0    = (const float*)d_in[12];
    const float* Wout  = (const float*)d_in[13];
    const float* bout  = (const float*)d_in[14];
    const float* trans = (const float*)d_in[15];
    float* out = (float*)d_out;

    k_init<<<64, 256>>>(h0);
    dim3 gg(16, 128, 2);
    k_gemm<<<gg, 256>>>(sent, lens, emb, Wihf, Wihb, bihf, bhhf, bihb, bhhb);
    k_lstm<<<128, 256>>>(Whhf, Whhb, c0, lens);
    k_feats<<<1024, 128>>>(Wout, bout);
    k_viterbi<<<4, 128>>>(trans, lens, out);
}